// round 11
// baseline (speedup 1.0000x reference)
#include <cuda_runtime.h>

// Problem constants (fixed by dataset: B=16, H=1024, W=2048, G=8, C=19)
#define NB      524288          // number of 8x8 label blocks = 16*128*256
#define NC      19
#define WID     2048
#define HEI     1024
#define GS      8
#define BLOCKS_PER_TILE 64
#define NTILES  (NB/BLOCKS_PER_TILE)           // 8192
#define F_PER_TILE (BLOCKS_PER_TILE*NC)        // 1216 floats
#define V_PER_TILE (F_PER_TILE/4)              // 304 float4

// Allocation-free scratch (__device__ globals per harness rules)
__device__ double       g_partials[NTILES];
__device__ unsigned int g_count = 0;           // self-resetting completion counter

// Numerically stable softplus: max(x,0) + log(1 + exp(-|x|))
__device__ __forceinline__ float softplus_f(float x)
{
    float e = __expf(-fabsf(x));
    return fmaxf(x, 0.0f) + __logf(1.0f + e);
}

// ---------------------------------------------------------------------------
// Small-tile fused kernel: 64 label blocks per CTA (8192 CTAs).
//   phase 1: tile's 16KB pixel strip read DENSE (lane-consecutive int4,
//            4 wavefronts per warp-LDG); masks via shfl pair-merge + smem
//            atomicOr (commutative -> deterministic)
//   phase 2: single preds pass, softplus + mask correction fused (no reload)
// Low MLP_p1 (~5) and short T_CTA minimize cross-CTA l1tex-queue spread
// and the ragged DRAM wind-down tail.
// ---------------------------------------------------------------------------
__global__ void __launch_bounds__(256)
fused_kernel(const int*   __restrict__ tgt,
             const float* __restrict__ preds,
             float*       __restrict__ out)
{
    __shared__ unsigned int sm_mask[BLOCKS_PER_TILE + 1];   // +pad entry
    __shared__ float  ws[8];
    __shared__ double sh[256];

    const unsigned int tid  = threadIdx.x;
    const unsigned int lane = tid & 31u;
    const unsigned int wix  = tid >> 5;
    const unsigned int tile = blockIdx.x;

    // zero mask slots (incl. pad) before atomicOr
    if (tid <= BLOCKS_PER_TILE) sm_mask[tid] = 0u;

    // ---- Phase 1: dense targets read ----
    // Tile strip: 8 rows x 512 px (16KB) at (image b, block-row bh, col bw0*8).
    unsigned int bw0 = (tile & 3u) << 6;           // 0,64,128,192
    unsigned int bh  = (tile >> 2) & 127u;
    unsigned int b   = tile >> 9;
    size_t rowbase = ((size_t)(b * HEI + bh * GS)) * WID + (size_t)bw0 * GS;
    const int4* tp = (const int4*)(tgt + rowbase);  // 16B aligned

    __syncthreads();                                // zeroing visible before atomics

    unsigned int m = 0u;
#pragma unroll
    for (int k = 0; k < 4; k++) {
        unsigned int idx = tid + (unsigned int)k * 256u;   // 0..1023 int4 of strip
        unsigned int r    = idx >> 7;                      // strip row 0..7
        unsigned int col4 = idx & 127u;                    // int4 within row
        int4 v = __ldcs(&tp[r * (WID / 4) + col4]);
        m |= (1u << v.x) | (1u << v.y) | (1u << v.z) | (1u << v.w);
    }
    // lane^1 covers the other 16B half of the same block -> merge
    m |= __shfl_xor_sync(0xffffffffu, m, 1);
    // two warps (even/odd strip rows) contribute per block -> atomicOr
    if ((tid & 1u) == 0u)
        atomicOr(&sm_mask[(tid & 127u) >> 1], m);
    __syncthreads();

    // ---- Phase 2: preds pass, softplus + correction fused ----
    const float4* pv = (const float4*)(preds + (size_t)tile * F_PER_TILE);
    float s = 0.0f;
#pragma unroll
    for (int it = 0; it < 2; it++) {
        unsigned int j = tid + (unsigned int)it * 256u;
        if (it == 1 && tid >= (V_PER_TILE - 256)) break;   // tail: tid < 48
        unsigned int e0 = j * 4u;
        unsigned int q  = e0 / 19u;                  // 0..63 (magic div)
        unsigned int c0 = e0 - q * 19u;              // 0..18
        unsigned int mm = (sm_mask[q] | (sm_mask[q + 1] << 19)) >> c0;

        float4 x = __ldcs(&pv[j]);
        s += softplus_f(x.x) + softplus_f(x.y)
           + softplus_f(x.z) + softplus_f(x.w);
        if (mm & 1u) s -= x.x;
        if (mm & 2u) s -= x.y;
        if (mm & 4u) s -= x.z;
        if (mm & 8u) s -= x.w;
    }

    // ---- CTA reduction -> double partial ----
#pragma unroll
    for (int o = 16; o > 0; o >>= 1)
        s += __shfl_xor_sync(0xffffffffu, s, o);
    if (lane == 0u) ws[wix] = s;
    __syncthreads();
    if (tid < 32u) {
        float v = (tid < 8u) ? ws[tid] : 0.0f;
#pragma unroll
        for (int o = 4; o > 0; o >>= 1)
            v += __shfl_xor_sync(0xffffffffu, v, o);
        if (tid == 0u) {
            g_partials[tile] = (double)v;
            __threadfence();
            unsigned int done = atomicAdd(&g_count, 1u);
            ws[0] = (done == (unsigned int)(NTILES - 1)) ? 1.0f : 0.0f;
        }
    }
    __syncthreads();
    if (ws[0] == 0.0f) return;

    // ---- Last CTA: deterministic final reduction over all partials ----
    double d = 0.0;
    for (unsigned int i = tid; i < (unsigned int)NTILES; i += 256u)
        d += g_partials[i];
    sh[tid] = d;
    __syncthreads();
#pragma unroll
    for (int o = 128; o > 0; o >>= 1) {
        if (tid < (unsigned int)o) sh[tid] += sh[tid + o];
        __syncthreads();
    }
    if (tid == 0) {
        out[0] = (float)(sh[0] / ((double)NB * (double)NC));
        g_count = 0;                         // reset for next graph replay
    }
}

// ---------------------------------------------------------------------------
extern "C" void kernel_launch(void* const* d_in, const int* in_sizes, int n_in,
                              void* d_out, int out_size)
{
    const float* preds = (const float*)d_in[0];
    const int*   tgt   = (const int*)d_in[1];
    // d_in[2] = grid_size (always 8 for this problem's shapes)

    fused_kernel<<<NTILES, 256>>>(tgt, preds, (float*)d_out);
}

// round 12
// speedup vs baseline: 1.1910x; 1.1910x over previous
#include <cuda_runtime.h>
#include <cstdint>

// Problem constants (fixed by dataset: B=16, H=1024, W=2048, G=8, C=19)
#define NB      524288
#define NC      19
#define WID     2048
#define HEI     1024
#define GS      8
#define BLOCKS_PER_TILE 128                    // half a block-row
#define NTILES  (NB/BLOCKS_PER_TILE)           // 4096
#define TGT_ROW_BYTES 4096                     // 1024 px * 4B per strip row
#define TGT_BYTES (8*TGT_ROW_BYTES)            // 32768
#define PRED_BYTES (BLOCKS_PER_TILE*NC*4)      // 9728 (16B multiple)
#define STAGE_BYTES (TGT_BYTES + PRED_BYTES)   // 42496
#define NSTAGE  2
#define GRID    304                            // 2 CTAs per SM (152 SMs)
#define V_PER_TILE (BLOCKS_PER_TILE*NC/4)      // 608 float4

// Allocation-free scratch (__device__ globals per harness rules)
__device__ double       g_partials[GRID];
__device__ unsigned int g_count = 0;           // self-resetting completion counter

// Numerically stable softplus: max(x,0) + log(1 + exp(-|x|))
__device__ __forceinline__ float softplus_f(float x)
{
    float e = __expf(-fabsf(x));
    return fmaxf(x, 0.0f) + __logf(1.0f + e);
}

__device__ __forceinline__ void mbar_init(uint32_t mbar, unsigned count)
{
    asm volatile("mbarrier.init.shared.b64 [%0], %1;" :: "r"(mbar), "r"(count) : "memory");
}

__device__ __forceinline__ void mbar_wait(uint32_t mbar, unsigned phase)
{
    asm volatile(
        "{\n\t.reg .pred P;\n\t"
        "WAIT_%=:\n\t"
        "mbarrier.try_wait.parity.acquire.cta.shared::cta.b64 P, [%0], %1, 0x989680;\n\t"
        "@P bra DONE_%=;\n\t"
        "bra WAIT_%=;\n\t"
        "DONE_%=:\n\t}"
        :: "r"(mbar), "r"(phase) : "memory");
}

__device__ __forceinline__ void bulk_cp(uint32_t dst_smem, const void* src,
                                        unsigned bytes, uint32_t mbar)
{
    asm volatile(
        "cp.async.bulk.shared::cluster.global.mbarrier::complete_tx::bytes "
        "[%0], [%1], %2, [%3];"
        :: "r"(dst_smem), "l"(src), "r"(bytes), "r"(mbar) : "memory");
}

// Issue one tile's loads: expect_tx + 8 target-row copies + 1 preds copy.
__device__ __forceinline__ void issue_tile(const int* tgt, const float* preds,
                                           unsigned tile, uint32_t stage, uint32_t mbar)
{
    asm volatile("mbarrier.arrive.expect_tx.shared.b64 _, [%0], %1;"
                 :: "r"(mbar), "r"((unsigned)STAGE_BYTES) : "memory");
    unsigned half = tile & 1u;
    unsigned bh   = (tile >> 1) & 127u;
    unsigned bimg = tile >> 8;
    const char* tsrc = (const char*)(tgt
        + ((size_t)(bimg * HEI + bh * GS)) * WID + (size_t)half * 1024u);
#pragma unroll
    for (int r = 0; r < 8; r++)
        bulk_cp(stage + r * TGT_ROW_BYTES, tsrc + (size_t)r * WID * 4,
                TGT_ROW_BYTES, mbar);
    bulk_cp(stage + TGT_BYTES, (const char*)preds + (size_t)tile * PRED_BYTES,
            PRED_BYTES, mbar);
}

// ---------------------------------------------------------------------------
// TMA double-buffered fused kernel. 304 persistent-ish CTAs, static tile
// assignment (tile = cta, cta+304, ...). TMA engine streams targets+preds
// into smem; warps compute masks + softplus entirely from smem. DRAM demand
// is decoupled from warp scoreboards -> continuous HBM pull.
// ---------------------------------------------------------------------------
__global__ void __launch_bounds__(256)
fused_kernel(const int*   __restrict__ tgt,
             const float* __restrict__ preds,
             float*       __restrict__ out)
{
    extern __shared__ char stage_mem[];                 // NSTAGE * STAGE_BYTES
    __shared__ unsigned long long mbar_store[NSTAGE];
    __shared__ unsigned int sm_mask[BLOCKS_PER_TILE + 1];
    __shared__ float  ws[8];
    __shared__ double sh[256];

    const unsigned tid  = threadIdx.x;
    const unsigned lane = tid & 31u;
    const unsigned wix  = tid >> 5;
    const unsigned cta  = blockIdx.x;

    const uint32_t stage0 = (uint32_t)__cvta_generic_to_shared(stage_mem);
    const uint32_t mb0    = (uint32_t)__cvta_generic_to_shared(&mbar_store[0]);
    const uint32_t mb1    = (uint32_t)__cvta_generic_to_shared(&mbar_store[1]);

    if (tid == 0) {
        mbar_init(mb0, 1);
        mbar_init(mb1, 1);
        asm volatile("fence.proxy.async.shared::cta;" ::: "memory");
        // Prologue: fill both stages (every CTA has >= 13 tiles)
        issue_tile(tgt, preds, cta,        stage0,               mb0);
        issue_tile(tgt, preds, cta + GRID, stage0 + STAGE_BYTES, mb1);
    }
    __syncthreads();

    unsigned ph0 = 0, ph1 = 0;
    float s = 0.0f;
    unsigned n = 0;

    for (unsigned tile = cta; tile < NTILES; tile += GRID, n++) {
        const unsigned k = n & 1u;
        const uint32_t  stg  = stage0 + k * STAGE_BYTES;
        const char*     stgp = stage_mem + k * STAGE_BYTES;
        const uint32_t  mb   = k ? mb1 : mb0;

        // wait for this stage's data
        if (k) { mbar_wait(mb, ph1); ph1 ^= 1u; }
        else   { mbar_wait(mb, ph0); ph0 ^= 1u; }

        // ---- masks: thread pair (2p, 2p+1) covers block p (16B halves) ----
        unsigned p = tid >> 1, h = tid & 1u;
        unsigned m = 0u;
#pragma unroll
        for (int r = 0; r < 8; r++) {
            int4 v = *(const int4*)(stgp + r * TGT_ROW_BYTES + p * 32u + h * 16u);
            m |= (1u << v.x) | (1u << v.y) | (1u << v.z) | (1u << v.w);
        }
        m |= __shfl_xor_sync(0xffffffffu, m, 1);
        __syncthreads();                 // prev tile's sm_mask readers done
        if (h == 0u) sm_mask[p] = m;
        if (tid == 0u) sm_mask[BLOCKS_PER_TILE] = 0u;
        __syncthreads();                 // masks visible

        // ---- preds: 608 float4 from smem, softplus + correction ----
        const float4* pvs = (const float4*)(stgp + TGT_BYTES);
#pragma unroll
        for (int it = 0; it < 3; it++) {
            unsigned j = tid + (unsigned)it * 256u;
            if (it == 2 && tid >= (V_PER_TILE - 512)) break;   // tail: tid < 96
            unsigned e0 = j * 4u;
            unsigned q  = e0 / 19u;                 // 0..127 (magic div)
            unsigned c0 = e0 - q * 19u;             // 0..18
            unsigned mm = (sm_mask[q] | (sm_mask[q + 1] << 19)) >> c0;
            float4 x = pvs[j];
            s += softplus_f(x.x) + softplus_f(x.y)
               + softplus_f(x.z) + softplus_f(x.w);
            if (mm & 1u) s -= x.x;
            if (mm & 2u) s -= x.y;
            if (mm & 4u) s -= x.z;
            if (mm & 8u) s -= x.w;
        }
        __syncthreads();                 // all smem reads of this stage done

        // refill this stage with tile + 2*GRID
        unsigned nt = tile + 2u * GRID;
        if (tid == 0u && nt < NTILES)
            issue_tile(tgt, preds, nt, stg, mb);
    }

    // ---- per-CTA fixed-tree reduction -> double partial ----
#pragma unroll
    for (int o = 16; o > 0; o >>= 1)
        s += __shfl_xor_sync(0xffffffffu, s, o);
    if (lane == 0u) ws[wix] = s;
    __syncthreads();
    if (tid < 32u) {
        float v = (tid < 8u) ? ws[tid] : 0.0f;
#pragma unroll
        for (int o = 4; o > 0; o >>= 1)
            v += __shfl_xor_sync(0xffffffffu, v, o);
        if (tid == 0u) {
            g_partials[cta] = (double)v;
            __threadfence();
            unsigned done = atomicAdd(&g_count, 1u);
            ws[0] = (done == (unsigned)(GRID - 1)) ? 1.0f : 0.0f;
        }
    }
    __syncthreads();
    if (ws[0] == 0.0f) return;

    // ---- Last CTA: deterministic final reduction over CTA partials ----
    double d = 0.0;
    for (unsigned i = tid; i < (unsigned)GRID; i += 256u)
        d += g_partials[i];
    sh[tid] = d;
    __syncthreads();
#pragma unroll
    for (int o = 128; o > 0; o >>= 1) {
        if (tid < (unsigned)o) sh[tid] += sh[tid + o];
        __syncthreads();
    }
    if (tid == 0) {
        out[0] = (float)(sh[0] / ((double)NB * (double)NC));
        g_count = 0;                     // reset for next graph replay
    }
}

// ---------------------------------------------------------------------------
extern "C" void kernel_launch(void* const* d_in, const int* in_sizes, int n_in,
                              void* d_out, int out_size)
{
    const float* preds = (const float*)d_in[0];
    const int*   tgt   = (const int*)d_in[1];
    // d_in[2] = grid_size (always 8 for this problem's shapes)

    static int smem_set = 0;
    if (!smem_set) {
        cudaFuncSetAttribute(fused_kernel,
                             cudaFuncAttributeMaxDynamicSharedMemorySize,
                             NSTAGE * STAGE_BYTES);
        smem_set = 1;
    }
    fused_kernel<<<GRID, 256, NSTAGE * STAGE_BYTES>>>(tgt, preds, (float*)d_out);
}